// round 9
// baseline (speedup 1.0000x reference)
#include <cuda_runtime.h>

// out[b,s,e] = sum_h cs[b,s,e,h] * W[e,h] + bias[e]
// B=4, S=512, E=64, H=1024 -> ROWS = 131072 reductions over 1024 contiguous floats.
// HBM-bound streaming at the B300 practical ceiling (~6.8 TB/s). R8: switch the
// stream to 256-bit loads (ld.global.v8.f32, sm_100+ -> LDG.E.256): half the
// LDG issue count and LSU queue slots per byte, same 4KB in flight per warp.
// Shape otherwise identical to R4/R7 (one warp per row, 64-thr CTAs, .cs
// streaming hint, W via nc path).

#define E_DIM 64
#define H_DIM 1024
#define HV8   (H_DIM / 8)      // 128 x 8-float groups per row
#define WARPS_PER_BLOCK 2

struct f8 { float v[8]; };

__device__ __forceinline__ f8 ldcs_v8(const float* p) {
    f8 r;
    asm volatile("ld.global.cs.v8.f32 {%0,%1,%2,%3,%4,%5,%6,%7}, [%8];"
                 : "=f"(r.v[0]), "=f"(r.v[1]), "=f"(r.v[2]), "=f"(r.v[3]),
                   "=f"(r.v[4]), "=f"(r.v[5]), "=f"(r.v[6]), "=f"(r.v[7])
                 : "l"(p));
    return r;
}

__device__ __forceinline__ f8 ldnc_v8(const float* p) {
    f8 r;
    asm volatile("ld.global.nc.v8.f32 {%0,%1,%2,%3,%4,%5,%6,%7}, [%8];"
                 : "=f"(r.v[0]), "=f"(r.v[1]), "=f"(r.v[2]), "=f"(r.v[3]),
                   "=f"(r.v[4]), "=f"(r.v[5]), "=f"(r.v[6]), "=f"(r.v[7])
                 : "l"(p));
    return r;
}

__device__ __forceinline__ void stcs_f32(float* p, float v) {
    asm volatile("st.global.cs.f32 [%0], %1;" :: "l"(p), "f"(v) : "memory");
}

__global__ __launch_bounds__(WARPS_PER_BLOCK * 32)
void Cell_to_Entity_78735340470739_kernel(
    const float* __restrict__ cs,     // [ROWS * H]
    const float* __restrict__ W,      // [E * H]
    const float* __restrict__ bias,   // [E]
    float*       __restrict__ out)    // [ROWS]
{
    const int warp = threadIdx.x >> 5;
    const int lane = threadIdx.x & 31;
    const int row  = blockIdx.x * WARPS_PER_BLOCK + warp;

    const int e = row & (E_DIM - 1);

    const float* __restrict__ x = cs + (size_t)row * H_DIM;
    const float* __restrict__ w = W  + (size_t)e   * H_DIM;

    float acc = 0.0f;
#pragma unroll
    for (int i = 0; i < 4; ++i) {
        const int off = (lane + 32 * i) * 8;     // 32B-aligned per lane
        f8 a = ldcs_v8(&x[off]);                 // LDG.E.256 streaming
        f8 b = ldnc_v8(&w[off]);                 // hot in L1/L2
        float s0 = a.v[0] * b.v[0] + a.v[1] * b.v[1];
        float s1 = a.v[2] * b.v[2] + a.v[3] * b.v[3];
        float s2 = a.v[4] * b.v[4] + a.v[5] * b.v[5];
        float s3 = a.v[6] * b.v[6] + a.v[7] * b.v[7];
        acc += (s0 + s1) + (s2 + s3);
    }

    // bias fetched before the reduction chain so it overlaps the shuffles
    const float be = __ldg(&bias[e]);

    // warp reduction
#pragma unroll
    for (int off = 16; off > 0; off >>= 1)
        acc += __shfl_xor_sync(0xffffffffu, acc, off);

    if (lane == 0)
        stcs_f32(&out[row], acc + be);
}

extern "C" void kernel_launch(void* const* d_in, const int* in_sizes, int n_in,
                              void* d_out, int out_size)
{
    const float* cs   = (const float*)d_in[0];   // [B,S,E,H] float32
    const float* W    = (const float*)d_in[1];   // [E,H]     float32
    const float* bias = (const float*)d_in[2];   // [E]       float32
    float*       out  = (float*)d_out;           // [B,S,E]   float32

    const int rows   = out_size;                 // B*S*E = 131072
    const int blocks = rows / WARPS_PER_BLOCK;   // 65536

    Cell_to_Entity_78735340470739_kernel<<<blocks, WARPS_PER_BLOCK * 32>>>(cs, W, bias, out);
}